// round 6
// baseline (speedup 1.0000x reference)
#include <cuda_runtime.h>

#define TS 96
#define NNODE 1024
#define GF 128
#define HID 512
#define NE 32768
#define INW 64
#define D2W 56
#define KFC (NNODE*GF)

// ---------------- static device scratch (no allocations allowed) ----------------
__device__ float g_buf0[TS*NNODE*GF];   // 50.3 MB  (GEMM outputs)
__device__ float g_buf1[TS*NNODE*GF];   // 50.3 MB  (message-passing outputs)
__device__ int   g_ecnt[TS*NNODE];
__device__ int   g_offs[TS*NNODE];
__device__ int   g_cursor[TS*NNODE];
__device__ float g_dinv[TS*NNODE];
__device__ int   g_csrc[TS*NE];         // 12.6 MB CSR src lists
__device__ float g_gpre[TS*D2W];
__device__ float g_prega[TS*4*HID];     // LSTM input-side gate preactivations
__device__ float g_Wht[4*HID*HID];      // transposed recurrent weights [jp][k]
__device__ float g_Wit[4*HID*INW];
__device__ float g_Wgt[4*HID*D2W];
__device__ float g_bpre[4*HID];
__device__ float g_hbuf[2*HID];         // h ping-pong
__device__ unsigned g_bar;

// ---------------- init: zero everything that accumulates ----------------
__global__ void k_init() {
    int idx = blockIdx.x*blockDim.x + threadIdx.x;
    if (idx < TS*NNODE) g_ecnt[idx] = 0;
    if (idx < TS*D2W)   g_gpre[idx] = 0.f;
    if (idx < 2*HID)    g_hbuf[idx] = 0.f;
    if (idx == 0)       g_bar = 0u;
}

// ---------------- degree histogram over dst (edge_index is int32!) ----------------
__global__ void k_ecnt(const int* __restrict__ ei) {
    int idx = blockIdx.x*blockDim.x + threadIdx.x;
    if (idx >= TS*NE) return;
    int t = idx / NE, e = idx - t*NE;
    int dst = ei[t*2*NE + NE + e] & (NNODE-1);
    atomicAdd(&g_ecnt[t*NNODE + dst], 1);
}

// ---------------- per-t exclusive scan (1024 threads, Hillis-Steele) + dinv ----------------
__global__ void k_scan() {
    int t = blockIdx.x;
    int n = threadIdx.x;
    __shared__ int sb[NNODE];
    int c = g_ecnt[t*NNODE + n];
    sb[n] = c;
    g_dinv[t*NNODE + n] = rsqrtf((float)(c + 1));  // deg includes self-loop, >= 1
    for (int off = 1; off < NNODE; off <<= 1) {
        __syncthreads();
        int v = (n >= off) ? sb[n - off] : 0;
        __syncthreads();
        sb[n] += v;
    }
    __syncthreads();
    int excl = sb[n] - c;
    g_offs[t*NNODE + n]   = excl;
    g_cursor[t*NNODE + n] = excl;
}

// ---------------- CSR fill (bucket by dst) ----------------
__global__ void k_fill(const int* __restrict__ ei) {
    int idx = blockIdx.x*blockDim.x + threadIdx.x;
    if (idx >= TS*NE) return;
    int t = idx / NE, e = idx - t*NE;
    int src = ei[t*2*NE + e] & (NNODE-1);
    int dst = ei[t*2*NE + NE + e] & (NNODE-1);
    int pos = atomicAdd(&g_cursor[t*NNODE + dst], 1);
    g_csrc[(size_t)t*NE + (pos & (NE-1))] = src;
}

// ---------------- batched SGEMM: g_buf0[t] = A[t] @ B, N fixed = 128 ----------------
// FIRST=true : A = external x_nodes, K = 1024
// FIRST=false: A = g_buf1 (conv1 output), K = 128
template<bool FIRST>
__global__ __launch_bounds__(256)
void k_gemm(const float* __restrict__ Aext, const float* __restrict__ B) {
    constexpr int K = FIRST ? NNODE : GF;
    int t  = blockIdx.y;
    int m0 = blockIdx.x * 128;
    const float* At = (FIRST ? Aext : (const float*)g_buf1) + (size_t)t * NNODE * K;
    float*       Ct = g_buf0 + (size_t)t * NNODE * GF;
    __shared__ float As[16][128];
    __shared__ float Bs[16][128];
    int tid = threadIdx.x;
    int tx = tid & 15, ty = tid >> 4;
    float acc[8][8];
    #pragma unroll
    for (int i = 0; i < 8; i++)
        #pragma unroll
        for (int j = 0; j < 8; j++) acc[i][j] = 0.f;

    for (int kk = 0; kk < K; kk += 16) {
        #pragma unroll
        for (int l = 0; l < 2; l++) {
            int i   = tid*2 + l;          // 0..511
            int row = i >> 2;
            int kq  = (i & 3) * 4;
            float4 v = *(const float4*)(At + (size_t)(m0 + row)*K + kk + kq);
            As[kq+0][row] = v.x; As[kq+1][row] = v.y;
            As[kq+2][row] = v.z; As[kq+3][row] = v.w;
        }
        #pragma unroll
        for (int l = 0; l < 2; l++) {
            int i  = tid*2 + l;
            int r  = i >> 5;
            int c4 = (i & 31) * 4;
            *(float4*)&Bs[r][c4] = *(const float4*)(B + (size_t)(kk + r)*GF + c4);
        }
        __syncthreads();
        #pragma unroll
        for (int k = 0; k < 16; k++) {
            float a[8], bb[8];
            *(float4*)&a[0]  = *(float4*)&As[k][ty*8];
            *(float4*)&a[4]  = *(float4*)&As[k][ty*8 + 4];
            *(float4*)&bb[0] = *(float4*)&Bs[k][tx*8];
            *(float4*)&bb[4] = *(float4*)&Bs[k][tx*8 + 4];
            #pragma unroll
            for (int i = 0; i < 8; i++)
                #pragma unroll
                for (int j = 0; j < 8; j++) acc[i][j] += a[i]*bb[j];
        }
        __syncthreads();
    }
    #pragma unroll
    for (int i = 0; i < 8; i++) {
        float* cp = Ct + (size_t)(m0 + ty*8 + i)*GF + tx*8;
        float4 v0 = make_float4(acc[i][0], acc[i][1], acc[i][2], acc[i][3]);
        float4 v1 = make_float4(acc[i][4], acc[i][5], acc[i][6], acc[i][7]);
        *(float4*)cp       = v0;
        *(float4*)(cp + 4) = v1;
    }
}

// ---------------- GCN message passing via CSR gather: g_buf1 = Ahat * g_buf0 + bias ----------------
// H[t][n][f] = dn * ( Y[n][f]*dn + sum_{e in in(n)} Y[src_e][f]*dinv[src_e] ) + bias[f]
template<bool RELU>
__global__ void k_mp(const float* __restrict__ bias) {
    int t = blockIdx.y, n = blockIdx.x, f = threadIdx.x;
    const float* Yt = g_buf0 + (size_t)t * NNODE * GF;
    const float* dv = g_dinv + t*NNODE;
    const int*   cs = g_csrc + (size_t)t*NE;
    float dn  = dv[n];
    float acc = Yt[n*GF + f] * dn;
    int e   = g_offs[t*NNODE + n];
    int end = e + g_ecnt[t*NNODE + n];
    for (; e + 3 < end; e += 4) {
        int s0 = cs[e], s1 = cs[e+1], s2 = cs[e+2], s3 = cs[e+3];
        float y0 = Yt[s0*GF + f], y1 = Yt[s1*GF + f];
        float y2 = Yt[s2*GF + f], y3 = Yt[s3*GF + f];
        acc += y0*dv[s0] + y1*dv[s1] + y2*dv[s2] + y3*dv[s3];
    }
    for (; e < end; e++) {
        int s = cs[e];
        acc += Yt[s*GF + f] * dv[s];
    }
    float v = acc*dn + bias[f];
    if (RELU) v = fmaxf(v, 0.f);
    g_buf1[(size_t)t*NNODE*GF + n*GF + f] = v;
}

// ---------------- FC: g_gpre[96][56] += g_buf1[96][131072] @ Wfc[131072][56] (K-split) ----------------
__global__ void k_fc(const float* __restrict__ Wfc) {
    const float* Xh = g_buf1;
    __shared__ float As[96][65];
    __shared__ float Ws[64][57];
    int tid = threadIdx.x;
    int tt = tid >> 3, dd = tid & 7;   // 32 t-groups x 8 d-groups
    int k0 = blockIdx.x * 512;
    float acc[3][7];
    #pragma unroll
    for (int r = 0; r < 3; r++)
        #pragma unroll
        for (int j = 0; j < 7; j++) acc[r][j] = 0.f;

    for (int sub = 0; sub < 8; sub++) {
        int kk = k0 + sub*64;
        for (int i = tid; i < 96*64; i += 256) {
            int tr = i >> 6, kl = i & 63;
            As[tr][kl] = Xh[(size_t)tr*KFC + kk + kl];
        }
        for (int i = tid; i < 64*56; i += 256) {
            int kl = i / 56, d = i - kl*56;
            Ws[kl][d] = Wfc[(size_t)(kk + kl)*56 + d];
        }
        __syncthreads();
        for (int k = 0; k < 64; k++) {
            float a0 = As[tt*3+0][k], a1 = As[tt*3+1][k], a2 = As[tt*3+2][k];
            #pragma unroll
            for (int j = 0; j < 7; j++) {
                float w = Ws[k][dd*7 + j];
                acc[0][j] += a0*w; acc[1][j] += a1*w; acc[2][j] += a2*w;
            }
        }
        __syncthreads();
    }
    #pragma unroll
    for (int r = 0; r < 3; r++)
        #pragma unroll
        for (int j = 0; j < 7; j++)
            atomicAdd(&g_gpre[(tt*3 + r)*D2W + dd*7 + j], acc[r][j]);
}

// ---------------- transpose LSTM weights into [jp = col*4+gate][k] layout ----------------
__global__ void k_trans(const float* __restrict__ Wii, const float* __restrict__ Wgi,
                        const float* __restrict__ Whi, const float* __restrict__ bi,
                        const float* __restrict__ Wif, const float* __restrict__ Wgf,
                        const float* __restrict__ Whf, const float* __restrict__ bf,
                        const float* __restrict__ Wig, const float* __restrict__ Wgg,
                        const float* __restrict__ Whg, const float* __restrict__ bg,
                        const float* __restrict__ Wio, const float* __restrict__ Wgo,
                        const float* __restrict__ Who, const float* __restrict__ bo) {
    int jp   = blockIdx.x;
    int col  = jp >> 2;
    int gate = jp & 3;
    const float* Wh = (gate == 0) ? Whi : (gate == 1) ? Whf : (gate == 2) ? Whg : Who;
    const float* Wi = (gate == 0) ? Wii : (gate == 1) ? Wif : (gate == 2) ? Wig : Wio;
    const float* Wg = (gate == 0) ? Wgi : (gate == 1) ? Wgf : (gate == 2) ? Wgg : Wgo;
    const float* bb = (gate == 0) ? bi  : (gate == 1) ? bf  : (gate == 2) ? bg  : bo;
    for (int k = threadIdx.x; k < HID; k += blockDim.x)
        g_Wht[(size_t)jp*HID + k] = Wh[(size_t)k*HID + col];
    if (threadIdx.x < INW) g_Wit[jp*INW + threadIdx.x] = Wi[threadIdx.x*HID + col];
    if (threadIdx.x < D2W) g_Wgt[jp*D2W + threadIdx.x] = Wg[threadIdx.x*HID + col];
    if (threadIdx.x == 0)  g_bpre[jp] = bb[col];
}

// ---------------- input-side gate preactivations: pre[t][jp] = b + x_t.Wi + g.Wg ----------------
__global__ void k_pre(const float* __restrict__ x_in, const float* __restrict__ bfc) {
    int t  = blockIdx.y;
    int jp = blockIdx.x*blockDim.x + threadIdx.x;
    __shared__ float xg[INW];
    __shared__ float gg[D2W];
    if (threadIdx.x < INW) xg[threadIdx.x] = x_in[t*INW + threadIdx.x];
    if (threadIdx.x < D2W)
        gg[threadIdx.x] = fmaxf(g_gpre[t*D2W + threadIdx.x] + bfc[threadIdx.x], 0.f);
    __syncthreads();
    float acc = g_bpre[jp];
    const float* wi = g_Wit + jp*INW;
    #pragma unroll
    for (int k = 0; k < INW; k++) acc += xg[k]*wi[k];
    const float* wg = g_Wgt + jp*D2W;
    #pragma unroll
    for (int k = 0; k < D2W; k++) acc += gg[k]*wg[k];
    g_prega[t*4*HID + jp] = acc;
}

// ---------------- persistent LSTM: 64 blocks, grid barrier per step ----------------
__device__ __forceinline__ float sigm(float x) { return 1.f / (1.f + expf(-x)); }

__global__ __launch_bounds__(256, 1)
void k_lstm(float* __restrict__ out, int write_hc) {
    int tid = threadIdx.x, b = blockIdx.x;
    int o_local = tid >> 3;       // 0..31 outputs per block
    int s       = tid & 7;        // 8-way split of the 512 dot
    int jp      = b*32 + o_local; // = col*4 + gate
    float w[64];
    #pragma unroll
    for (int j = 0; j < 64; j++)
        w[j] = g_Wht[(size_t)jp*HID + j*8 + s];   // strided k-split: bank-conflict-free LDS

    __shared__ float h_sh[HID];
    __shared__ float gates_sh[32];
    __shared__ float c_sh[8];
    if (tid < 8) c_sh[tid] = 0.f;

    for (int t = 0; t < TS; t++) {
        h_sh[tid]       = g_hbuf[(t & 1)*HID + tid];
        h_sh[tid + 256] = g_hbuf[(t & 1)*HID + tid + 256];
        __syncthreads();
        float acc = 0.f;
        #pragma unroll
        for (int j = 0; j < 64; j++) acc += w[j] * h_sh[j*8 + s];
        acc += __shfl_down_sync(0xffffffffu, acc, 4);
        acc += __shfl_down_sync(0xffffffffu, acc, 2);
        acc += __shfl_down_sync(0xffffffffu, acc, 1);
        if (s == 0) gates_sh[o_local] = acc + g_prega[t*4*HID + jp];
        __syncthreads();
        if (tid < 8) {
            float gi = gates_sh[tid*4 + 0];
            float gf = gates_sh[tid*4 + 1];
            float gc = gates_sh[tid*4 + 2];
            float go = gates_sh[tid*4 + 3];
            float i_ = sigm(gi), f_ = sigm(gf), o_ = sigm(go);
            float c  = f_*c_sh[tid] + i_*tanhf(gc);
            c_sh[tid] = c;
            float h = o_*tanhf(c);
            int col = b*8 + tid;
            g_hbuf[((t + 1) & 1)*HID + col] = h;
            out[t*HID + col] = h;
            if (t == TS - 1 && write_hc) {
                out[TS*HID + col]       = h;
                out[TS*HID + HID + col] = c;
            }
            __threadfence();
        }
        __syncthreads();
        if (tid == 0) {
            __threadfence();
            atomicAdd(&g_bar, 1u);
            unsigned target = (unsigned)(t + 1) * 64u;
            while (*(volatile unsigned*)&g_bar < target) __nanosleep(64);
            __threadfence();
        }
        __syncthreads();
    }
}

// ---------------- host launch: pure kernel launches only ----------------
extern "C" void kernel_launch(void* const* d_in, const int* in_sizes, int n_in,
                              void* d_out, int out_size) {
    const float* input  = (const float*)d_in[0];
    const float* xnodes = (const float*)d_in[1];
    const int*   ei     = (const int*)d_in[2];   // edge_index: int32 (JAX x64 disabled)
    const float* W1  = (const float*)d_in[3];
    const float* b1  = (const float*)d_in[4];
    const float* W2  = (const float*)d_in[5];
    const float* b2  = (const float*)d_in[6];
    const float* Wfc = (const float*)d_in[7];
    const float* bfc = (const float*)d_in[8];
    const float* Wii = (const float*)d_in[9],  *Wgi = (const float*)d_in[10];
    const float* Whi = (const float*)d_in[11], *bi  = (const float*)d_in[12];
    const float* Wif = (const float*)d_in[13], *Wgf = (const float*)d_in[14];
    const float* Whf = (const float*)d_in[15], *bf  = (const float*)d_in[16];
    const float* Wig = (const float*)d_in[17], *Wgg = (const float*)d_in[18];
    const float* Whg = (const float*)d_in[19], *bg  = (const float*)d_in[20];
    const float* Wio = (const float*)d_in[21], *Wgo = (const float*)d_in[22];
    const float* Who = (const float*)d_in[23], *bo  = (const float*)d_in[24];
    float* out = (float*)d_out;

    k_init<<<(TS*NNODE + 255)/256, 256>>>();
    k_ecnt<<<(TS*NE)/256, 256>>>(ei);
    k_scan<<<TS, NNODE>>>();
    k_fill<<<(TS*NE)/256, 256>>>(ei);

    // conv1: buf0 = x_nodes @ W1 ; buf1 = relu(Ahat*buf0 + b1)
    k_gemm<true><<<dim3(8, TS), 256>>>(xnodes, W1);
    k_mp<true><<<dim3(NNODE, TS), GF>>>(b1);
    // conv2: buf0 = buf1 @ W2 ; buf1 = Ahat*buf0 + b2
    k_gemm<false><<<dim3(8, TS), 256>>>(nullptr, W2);
    k_mp<false><<<dim3(NNODE, TS), GF>>>(b2);

    // g_gpre = buf1_flat @ Wfc (K-split, Wfc read exactly once)
    k_fc<<<256, 256>>>(Wfc);

    // LSTM weight transpose + input-side preactivations
    k_trans<<<4*HID, 128>>>(Wii, Wgi, Whi, bi, Wif, Wgf, Whf, bf,
                            Wig, Wgg, Whg, bg, Wio, Wgo, Who, bo);
    k_pre<<<dim3(8, TS), 256>>>(input, bfc);

    int whc = (out_size >= TS*HID + 2*HID) ? 1 : 0;
    k_lstm<<<64, 256>>>(out, whc);
}

// round 7
// speedup vs baseline: 1.2398x; 1.2398x over previous
#include <cuda_runtime.h>
#include <cuda_bf16.h>
#include <cstdint>

#define TS 96
#define NNODE 1024
#define GF 128
#define HID 512
#define NE 32768
#define INW 64
#define D2W 56
#define KFC (NNODE*GF)

// ---------------- static device scratch (no allocations allowed) ----------------
__device__ float g_buf0[TS*NNODE*GF];   // 50.3 MB  (GEMM outputs)
__device__ float g_buf1[TS*NNODE*GF];   // 50.3 MB  (message-passing outputs)
__device__ int   g_ecnt[TS*NNODE];
__device__ int   g_offs[TS*NNODE];
__device__ int   g_cursor[TS*NNODE];
__device__ float g_dinv[TS*NNODE];
__device__ int   g_csrc[TS*NE];         // 12.6 MB CSR src lists
__device__ float g_gpre[TS*D2W];
__device__ float g_prega[TS*4*HID];     // LSTM input-side gate preactivations
__device__ float g_Wht[4*HID*HID];      // transposed recurrent weights [jp][k]
__device__ float g_Wit[4*HID*INW];
__device__ float g_Wgt[4*HID*D2W];
__device__ float g_bpre[4*HID];
__device__ float g_hbuf[2*HID];         // h ping-pong
__device__ unsigned g_bar;

// ---------------- init: zero everything that accumulates ----------------
__global__ void k_init() {
    int idx = blockIdx.x*blockDim.x + threadIdx.x;
    if (idx < TS*NNODE) g_ecnt[idx] = 0;
    if (idx < TS*D2W)   g_gpre[idx] = 0.f;
    if (idx < 2*HID)    g_hbuf[idx] = 0.f;
    if (idx == 0)       g_bar = 0u;
}

// ---------------- degree histogram over dst (edge_index is int32) ----------------
__global__ void k_ecnt(const int* __restrict__ ei) {
    int idx = blockIdx.x*blockDim.x + threadIdx.x;
    if (idx >= TS*NE) return;
    int t = idx / NE, e = idx - t*NE;
    int dst = ei[t*2*NE + NE + e] & (NNODE-1);
    atomicAdd(&g_ecnt[t*NNODE + dst], 1);
}

// ---------------- per-t exclusive scan (1024 threads) + dinv ----------------
__global__ void k_scan() {
    int t = blockIdx.x;
    int n = threadIdx.x;
    __shared__ int sb[NNODE];
    int c = g_ecnt[t*NNODE + n];
    sb[n] = c;
    g_dinv[t*NNODE + n] = rsqrtf((float)(c + 1));  // deg includes self-loop, >= 1
    for (int off = 1; off < NNODE; off <<= 1) {
        __syncthreads();
        int v = (n >= off) ? sb[n - off] : 0;
        __syncthreads();
        sb[n] += v;
    }
    __syncthreads();
    int excl = sb[n] - c;
    g_offs[t*NNODE + n]   = excl;
    g_cursor[t*NNODE + n] = excl;
}

// ---------------- CSR fill (bucket by dst) ----------------
__global__ void k_fill(const int* __restrict__ ei) {
    int idx = blockIdx.x*blockDim.x + threadIdx.x;
    if (idx >= TS*NE) return;
    int t = idx / NE, e = idx - t*NE;
    int src = ei[t*2*NE + e] & (NNODE-1);
    int dst = ei[t*2*NE + NE + e] & (NNODE-1);
    int pos = atomicAdd(&g_cursor[t*NNODE + dst], 1);
    g_csrc[(size_t)t*NE + (pos & (NE-1))] = src;
}

// ---------------- bf16-split tensor-core GEMM ----------------
// C[t] = A[t] @ B via  Ahi@Bhi + Ahi@Blo + Alo@Bhi  (fp32 accum, ~1e-5 accuracy)
__device__ __forceinline__ uint32_t pack_bf2(float a, float b) {
    __nv_bfloat162 h = __floats2bfloat162_rn(a, b);  // .x=a (low half), .y=b
    return *(uint32_t*)&h;
}
__device__ __forceinline__ void mma16816(float* c, const uint32_t* a, const uint32_t* b) {
    asm volatile(
        "mma.sync.aligned.m16n8k16.row.col.f32.bf16.bf16.f32 "
        "{%0,%1,%2,%3}, {%4,%5,%6,%7}, {%8,%9}, {%0,%1,%2,%3};\n"
        : "+f"(c[0]), "+f"(c[1]), "+f"(c[2]), "+f"(c[3])
        : "r"(a[0]), "r"(a[1]), "r"(a[2]), "r"(a[3]), "r"(b[0]), "r"(b[1]));
}

template<bool FIRST>
__global__ __launch_bounds__(256)
void k_gemm_tc(const float* __restrict__ Aext, const float* __restrict__ B) {
    constexpr int K = FIRST ? NNODE : GF;
    const int t  = blockIdx.y;
    const int m0 = blockIdx.x * 128;
    const float* At = (FIRST ? Aext : (const float*)g_buf1) + (size_t)t * NNODE * K;
    float*       Ct = g_buf0 + (size_t)t * NNODE * GF;

    // [hi/lo][row][kpair 0..15 + 2 pad] packed bf16x2 words
    __shared__ uint32_t As32[2][128][18];
    __shared__ uint32_t Bs32[2][128][18];

    const int tid  = threadIdx.x;
    const int lane = tid & 31, wid = tid >> 5;
    const int mbase = (wid >> 1) * 32;   // 4 warps over M
    const int nbase = (wid & 1) * 64;    // 2 warps over N
    const int r = lane >> 2, q = lane & 3;

    float c[2][8][4];
    #pragma unroll
    for (int mt = 0; mt < 2; mt++)
        #pragma unroll
        for (int nt = 0; nt < 8; nt++)
            #pragma unroll
            for (int i = 0; i < 4; i++) c[mt][nt][i] = 0.f;

    for (int kk = 0; kk < K; kk += 32) {
        // ---- A tile 128x32 fp32 -> hi/lo bf16 pairs ----
        #pragma unroll
        for (int it = 0; it < 4; it++) {
            int idx = tid + it*256;
            int row = idx >> 3, c4 = idx & 7;
            float4 v = *(const float4*)(At + (size_t)(m0 + row)*K + kk + c4*4);
            float hx = __bfloat162float(__float2bfloat16(v.x));
            float hy = __bfloat162float(__float2bfloat16(v.y));
            float hz = __bfloat162float(__float2bfloat16(v.z));
            float hw = __bfloat162float(__float2bfloat16(v.w));
            As32[0][row][c4*2]   = pack_bf2(hx, hy);
            As32[0][row][c4*2+1] = pack_bf2(hz, hw);
            As32[1][row][c4*2]   = pack_bf2(v.x - hx, v.y - hy);
            As32[1][row][c4*2+1] = pack_bf2(v.z - hz, v.w - hw);
        }
        // ---- B tile 32x128 fp32 -> transposed [n][kpair] hi/lo ----
        #pragma unroll
        for (int it = 0; it < 2; it++) {
            int n4 = tid & 31;                 // n = n4*4
            int kp = (tid >> 5) + it*8;        // kpair 0..15
            const float* bp = B + (size_t)(kk + kp*2)*GF + n4*4;
            float4 v0 = *(const float4*)(bp);        // k even
            float4 v1 = *(const float4*)(bp + GF);   // k odd
            float a0[4] = {v0.x, v0.y, v0.z, v0.w};
            float a1[4] = {v1.x, v1.y, v1.z, v1.w};
            #pragma unroll
            for (int j = 0; j < 4; j++) {
                float h0 = __bfloat162float(__float2bfloat16(a0[j]));
                float h1 = __bfloat162float(__float2bfloat16(a1[j]));
                Bs32[0][n4*4 + j][kp] = pack_bf2(h0, h1);
                Bs32[1][n4*4 + j][kp] = pack_bf2(a0[j] - h0, a1[j] - h1);
            }
        }
        __syncthreads();
        // ---- two k16 steps ----
        #pragma unroll
        for (int s = 0; s < 2; s++) {
            uint32_t af[2][2][4];
            #pragma unroll
            for (int mt = 0; mt < 2; mt++)
                #pragma unroll
                for (int h = 0; h < 2; h++) {
                    int mrow = mbase + mt*16 + r;
                    af[mt][h][0] = As32[h][mrow    ][s*8 + q];
                    af[mt][h][1] = As32[h][mrow + 8][s*8 + q];
                    af[mt][h][2] = As32[h][mrow    ][s*8 + q + 4];
                    af[mt][h][3] = As32[h][mrow + 8][s*8 + q + 4];
                }
            #pragma unroll
            for (int nt = 0; nt < 8; nt++) {
                uint32_t bfr[2][2];
                #pragma unroll
                for (int h = 0; h < 2; h++) {
                    bfr[h][0] = Bs32[h][nbase + nt*8 + r][s*8 + q];
                    bfr[h][1] = Bs32[h][nbase + nt*8 + r][s*8 + q + 4];
                }
                #pragma unroll
                for (int mt = 0; mt < 2; mt++) {
                    mma16816(c[mt][nt], af[mt][0], bfr[0]);  // hi*hi
                    mma16816(c[mt][nt], af[mt][0], bfr[1]);  // hi*lo
                    mma16816(c[mt][nt], af[mt][1], bfr[0]);  // lo*hi
                }
            }
        }
        __syncthreads();
    }
    // ---- epilogue: fp32 store ----
    #pragma unroll
    for (int mt = 0; mt < 2; mt++) {
        #pragma unroll
        for (int nt = 0; nt < 8; nt++) {
            int row0 = m0 + mbase + mt*16 + r;
            int col  = nbase + nt*8 + 2*q;
            *(float2*)(Ct + (size_t)row0*GF + col)       = make_float2(c[mt][nt][0], c[mt][nt][1]);
            *(float2*)(Ct + (size_t)(row0 + 8)*GF + col) = make_float2(c[mt][nt][2], c[mt][nt][3]);
        }
    }
}

// ---------------- GCN message passing via CSR gather: g_buf1 = Ahat * g_buf0 + bias ----------------
template<bool RELU>
__global__ void k_mp(const float* __restrict__ bias) {
    int t = blockIdx.y, n = blockIdx.x, f = threadIdx.x;
    const float* Yt = g_buf0 + (size_t)t * NNODE * GF;
    const float* dv = g_dinv + t*NNODE;
    const int*   cs = g_csrc + (size_t)t*NE;
    float dn  = dv[n];
    float acc = Yt[n*GF + f] * dn;
    int e   = g_offs[t*NNODE + n];
    int end = e + g_ecnt[t*NNODE + n];
    for (; e + 3 < end; e += 4) {
        int s0 = cs[e], s1 = cs[e+1], s2 = cs[e+2], s3 = cs[e+3];
        float y0 = Yt[s0*GF + f], y1 = Yt[s1*GF + f];
        float y2 = Yt[s2*GF + f], y3 = Yt[s3*GF + f];
        acc += y0*dv[s0] + y1*dv[s1] + y2*dv[s2] + y3*dv[s3];
    }
    for (; e < end; e++) {
        int s = cs[e];
        acc += Yt[s*GF + f] * dv[s];
    }
    float v = acc*dn + bias[f];
    if (RELU) v = fmaxf(v, 0.f);
    g_buf1[(size_t)t*NNODE*GF + n*GF + f] = v;
}

// ---------------- FC: g_gpre[96][56] += g_buf1[96][131072] @ Wfc[131072][56] (K-split) ----------------
__global__ void k_fc(const float* __restrict__ Wfc) {
    const float* Xh = g_buf1;
    __shared__ float As[96][65];
    __shared__ float Ws[64][57];
    int tid = threadIdx.x;
    int tt = tid >> 3, dd = tid & 7;   // 32 t-groups x 8 d-groups
    int k0 = blockIdx.x * 512;
    float acc[3][7];
    #pragma unroll
    for (int r = 0; r < 3; r++)
        #pragma unroll
        for (int j = 0; j < 7; j++) acc[r][j] = 0.f;

    for (int sub = 0; sub < 8; sub++) {
        int kk = k0 + sub*64;
        for (int i = tid; i < 96*64; i += 256) {
            int tr = i >> 6, kl = i & 63;
            As[tr][kl] = Xh[(size_t)tr*KFC + kk + kl];
        }
        for (int i = tid; i < 64*56; i += 256) {
            int kl = i / 56, d = i - kl*56;
            Ws[kl][d] = Wfc[(size_t)(kk + kl)*56 + d];
        }
        __syncthreads();
        for (int k = 0; k < 64; k++) {
            float a0 = As[tt*3+0][k], a1 = As[tt*3+1][k], a2 = As[tt*3+2][k];
            #pragma unroll
            for (int j = 0; j < 7; j++) {
                float w = Ws[k][dd*7 + j];
                acc[0][j] += a0*w; acc[1][j] += a1*w; acc[2][j] += a2*w;
            }
        }
        __syncthreads();
    }
    #pragma unroll
    for (int r = 0; r < 3; r++)
        #pragma unroll
        for (int j = 0; j < 7; j++)
            atomicAdd(&g_gpre[(tt*3 + r)*D2W + dd*7 + j], acc[r][j]);
}

// ---------------- transpose LSTM weights into [jp = col*4+gate][k] layout ----------------
__global__ void k_trans(const float* __restrict__ Wii, const float* __restrict__ Wgi,
                        const float* __restrict__ Whi, const float* __restrict__ bi,
                        const float* __restrict__ Wif, const float* __restrict__ Wgf,
                        const float* __restrict__ Whf, const float* __restrict__ bf,
                        const float* __restrict__ Wig, const float* __restrict__ Wgg,
                        const float* __restrict__ Whg, const float* __restrict__ bg,
                        const float* __restrict__ Wio, const float* __restrict__ Wgo,
                        const float* __restrict__ Who, const float* __restrict__ bo) {
    int jp   = blockIdx.x;
    int col  = jp >> 2;
    int gate = jp & 3;
    const float* Wh = (gate == 0) ? Whi : (gate == 1) ? Whf : (gate == 2) ? Whg : Who;
    const float* Wi = (gate == 0) ? Wii : (gate == 1) ? Wif : (gate == 2) ? Wig : Wio;
    const float* Wg = (gate == 0) ? Wgi : (gate == 1) ? Wgf : (gate == 2) ? Wgg : Wgo;
    const float* bb = (gate == 0) ? bi  : (gate == 1) ? bf  : (gate == 2) ? bg  : bo;
    for (int k = threadIdx.x; k < HID; k += blockDim.x)
        g_Wht[(size_t)jp*HID + k] = Wh[(size_t)k*HID + col];
    if (threadIdx.x < INW) g_Wit[jp*INW + threadIdx.x] = Wi[threadIdx.x*HID + col];
    if (threadIdx.x < D2W) g_Wgt[jp*D2W + threadIdx.x] = Wg[threadIdx.x*HID + col];
    if (threadIdx.x == 0)  g_bpre[jp] = bb[col];
}

// ---------------- input-side gate preactivations: pre[t][jp] = b + x_t.Wi + g.Wg ----------------
__global__ void k_pre(const float* __restrict__ x_in, const float* __restrict__ bfc) {
    int t  = blockIdx.y;
    int jp = blockIdx.x*blockDim.x + threadIdx.x;
    __shared__ float xg[INW];
    __shared__ float gg[D2W];
    if (threadIdx.x < INW) xg[threadIdx.x] = x_in[t*INW + threadIdx.x];
    if (threadIdx.x < D2W)
        gg[threadIdx.x] = fmaxf(g_gpre[t*D2W + threadIdx.x] + bfc[threadIdx.x], 0.f);
    __syncthreads();
    float acc = g_bpre[jp];
    const float* wi = g_Wit + jp*INW;
    #pragma unroll
    for (int k = 0; k < INW; k++) acc += xg[k]*wi[k];
    const float* wg = g_Wgt + jp*D2W;
    #pragma unroll
    for (int k = 0; k < D2W; k++) acc += gg[k]*wg[k];
    g_prega[t*4*HID + jp] = acc;
}

// ---------------- persistent LSTM: 64 blocks, grid barrier per step ----------------
__device__ __forceinline__ float sigm(float x) { return 1.f / (1.f + expf(-x)); }

__global__ __launch_bounds__(256, 1)
void k_lstm(float* __restrict__ out, int write_hc) {
    int tid = threadIdx.x, b = blockIdx.x;
    int o_local = tid >> 3;       // 0..31 outputs per block
    int s       = tid & 7;        // 8-way split of the 512 dot
    int jp      = b*32 + o_local; // = col*4 + gate
    float w[64];
    #pragma unroll
    for (int j = 0; j < 64; j++)
        w[j] = g_Wht[(size_t)jp*HID + j*8 + s];

    __shared__ float h_sh[HID];
    __shared__ float gates_sh[32];
    __shared__ float c_sh[8];
    if (tid < 8) c_sh[tid] = 0.f;

    for (int t = 0; t < TS; t++) {
        h_sh[tid]       = g_hbuf[(t & 1)*HID + tid];
        h_sh[tid + 256] = g_hbuf[(t & 1)*HID + tid + 256];
        __syncthreads();
        float acc = 0.f;
        #pragma unroll
        for (int j = 0; j < 64; j++) acc += w[j] * h_sh[j*8 + s];
        acc += __shfl_down_sync(0xffffffffu, acc, 4);
        acc += __shfl_down_sync(0xffffffffu, acc, 2);
        acc += __shfl_down_sync(0xffffffffu, acc, 1);
        if (s == 0) gates_sh[o_local] = acc + g_prega[t*4*HID + jp];
        __syncthreads();
        if (tid < 8) {
            float gi = gates_sh[tid*4 + 0];
            float gf = gates_sh[tid*4 + 1];
            float gc = gates_sh[tid*4 + 2];
            float go = gates_sh[tid*4 + 3];
            float i_ = sigm(gi), f_ = sigm(gf), o_ = sigm(go);
            float cc = f_*c_sh[tid] + i_*tanhf(gc);
            c_sh[tid] = cc;
            float h = o_*tanhf(cc);
            int col = b*8 + tid;
            g_hbuf[((t + 1) & 1)*HID + col] = h;
            out[t*HID + col] = h;
            if (t == TS - 1 && write_hc) {
                out[TS*HID + col]       = h;
                out[TS*HID + HID + col] = cc;
            }
            __threadfence();
        }
        __syncthreads();
        if (tid == 0) {
            __threadfence();
            atomicAdd(&g_bar, 1u);
            unsigned target = (unsigned)(t + 1) * 64u;
            while (*(volatile unsigned*)&g_bar < target) __nanosleep(64);
            __threadfence();
        }
        __syncthreads();
    }
}

// ---------------- host launch: pure kernel launches only ----------------
extern "C" void kernel_launch(void* const* d_in, const int* in_sizes, int n_in,
                              void* d_out, int out_size) {
    const float* input  = (const float*)d_in[0];
    const float* xnodes = (const float*)d_in[1];
    const int*   ei     = (const int*)d_in[2];   // edge_index: int32
    const float* W1  = (const float*)d_in[3];
    const float* b1  = (const float*)d_in[4];
    const float* W2  = (const float*)d_in[5];
    const float* b2  = (const float*)d_in[6];
    const float* Wfc = (const float*)d_in[7];
    const float* bfc = (const float*)d_in[8];
    const float* Wii = (const float*)d_in[9],  *Wgi = (const float*)d_in[10];
    const float* Whi = (const float*)d_in[11], *bi  = (const float*)d_in[12];
    const float* Wif = (const float*)d_in[13], *Wgf = (const float*)d_in[14];
    const float* Whf = (const float*)d_in[15], *bf  = (const float*)d_in[16];
    const float* Wig = (const float*)d_in[17], *Wgg = (const float*)d_in[18];
    const float* Whg = (const float*)d_in[19], *bg  = (const float*)d_in[20];
    const float* Wio = (const float*)d_in[21], *Wgo = (const float*)d_in[22];
    const float* Who = (const float*)d_in[23], *bo  = (const float*)d_in[24];
    float* out = (float*)d_out;

    k_init<<<(TS*NNODE + 255)/256, 256>>>();
    k_ecnt<<<(TS*NE)/256, 256>>>(ei);
    k_scan<<<TS, NNODE>>>();
    k_fill<<<(TS*NE)/256, 256>>>(ei);

    // conv1: buf0 = x_nodes @ W1 ; buf1 = relu(Ahat*buf0 + b1)
    k_gemm_tc<true><<<dim3(8, TS), 256>>>(xnodes, W1);
    k_mp<true><<<dim3(NNODE, TS), GF>>>(b1);
    // conv2: buf0 = buf1 @ W2 ; buf1 = Ahat*buf0 + b2
    k_gemm_tc<false><<<dim3(8, TS), 256>>>(nullptr, W2);
    k_mp<false><<<dim3(NNODE, TS), GF>>>(b2);

    // g_gpre = buf1_flat @ Wfc (K-split, Wfc read exactly once)
    k_fc<<<256, 256>>>(Wfc);

    // LSTM weight transpose + input-side preactivations
    k_trans<<<4*HID, 128>>>(Wii, Wgi, Whi, bi, Wif, Wgf, Whf, bf,
                            Wig, Wgg, Whg, bg, Wio, Wgo, Who, bo);
    k_pre<<<dim3(8, TS), 256>>>(input, bfc);

    int whc = (out_size >= TS*HID + 2*HID) ? 1 : 0;
    k_lstm<<<64, 256>>>(out, whc);
}

// round 10
// speedup vs baseline: 1.2706x; 1.0249x over previous
#include <cuda_runtime.h>
#include <cuda_bf16.h>
#include <cstdint>

#define TS 96
#define NNODE 1024
#define GF 128
#define HID 512
#define NE 32768
#define INW 64
#define D2W 56
#define KFC (NNODE*GF)

// ---------------- static device scratch (no allocations allowed) ----------------
__device__ float g_buf0[TS*NNODE*GF];   // 50.3 MB  (GEMM outputs, pre-scaled by dinv)
__device__ float g_buf1[TS*NNODE*GF];   // 50.3 MB  (message-passing outputs)
__device__ int   g_ecnt[TS*NNODE];
__device__ int   g_offs[TS*NNODE];
__device__ int   g_cursor[TS*NNODE];
__device__ float g_dinv[TS*NNODE];
__device__ int   g_csrc[TS*NE];         // 12.6 MB CSR src lists
__device__ float g_gpre[TS*D2W];
__device__ float g_prega[TS*4*HID];     // LSTM input-side gate preactivations
__device__ float g_Wht[4*HID*HID];      // transposed recurrent weights [jp][k]
__device__ float g_Wit[4*HID*INW];
__device__ float g_Wgt[4*HID*D2W];
__device__ float g_bpre[4*HID];
__device__ float g_hbuf[2*HID];         // h ping-pong
__device__ unsigned g_bar;

// ---------------- init ----------------
__global__ void k_init() {
    int idx = blockIdx.x*blockDim.x + threadIdx.x;
    if (idx < TS*NNODE) g_ecnt[idx] = 0;
    if (idx < TS*D2W)   g_gpre[idx] = 0.f;
    if (idx < 2*HID)    g_hbuf[idx] = 0.f;
    if (idx == 0)       g_bar = 0u;
}

// ---------------- degree histogram over dst (edge_index is int32) ----------------
__global__ void k_ecnt(const int* __restrict__ ei) {
    int idx = blockIdx.x*blockDim.x + threadIdx.x;
    if (idx >= TS*NE) return;
    int t = idx / NE, e = idx - t*NE;
    int dst = ei[t*2*NE + NE + e] & (NNODE-1);
    atomicAdd(&g_ecnt[t*NNODE + dst], 1);
}

// ---------------- per-t exclusive scan + dinv ----------------
__global__ void k_scan() {
    int t = blockIdx.x;
    int n = threadIdx.x;
    __shared__ int sb[NNODE];
    int c = g_ecnt[t*NNODE + n];
    sb[n] = c;
    g_dinv[t*NNODE + n] = rsqrtf((float)(c + 1));
    for (int off = 1; off < NNODE; off <<= 1) {
        __syncthreads();
        int v = (n >= off) ? sb[n - off] : 0;
        __syncthreads();
        sb[n] += v;
    }
    __syncthreads();
    int excl = sb[n] - c;
    g_offs[t*NNODE + n]   = excl;
    g_cursor[t*NNODE + n] = excl;
}

// ---------------- CSR fill (bucket by dst) ----------------
__global__ void k_fill(const int* __restrict__ ei) {
    int idx = blockIdx.x*blockDim.x + threadIdx.x;
    if (idx >= TS*NE) return;
    int t = idx / NE, e = idx - t*NE;
    int src = ei[t*2*NE + e] & (NNODE-1);
    int dst = ei[t*2*NE + NE + e] & (NNODE-1);
    int pos = atomicAdd(&g_cursor[t*NNODE + dst], 1);
    g_csrc[(size_t)t*NE + (pos & (NE-1))] = src;
}

// ---------------- bf16-split tensor-core GEMM, epilogue scales by dinv ----------------
// g_buf0[t][n] = (A[t] @ B)[n] * dinv[t][n]
__device__ __forceinline__ uint32_t pack_bf2(float a, float b) {
    __nv_bfloat162 h = __floats2bfloat162_rn(a, b);
    return *(uint32_t*)&h;
}
__device__ __forceinline__ void mma16816(float* c, const uint32_t* a, const uint32_t* b) {
    asm volatile(
        "mma.sync.aligned.m16n8k16.row.col.f32.bf16.bf16.f32 "
        "{%0,%1,%2,%3}, {%4,%5,%6,%7}, {%8,%9}, {%0,%1,%2,%3};\n"
        : "+f"(c[0]), "+f"(c[1]), "+f"(c[2]), "+f"(c[3])
        : "r"(a[0]), "r"(a[1]), "r"(a[2]), "r"(a[3]), "r"(b[0]), "r"(b[1]));
}

template<bool FIRST>
__global__ __launch_bounds__(256)
void k_gemm_tc(const float* __restrict__ Aext, const float* __restrict__ B) {
    constexpr int K = FIRST ? NNODE : GF;
    const int t  = blockIdx.y;
    const int m0 = blockIdx.x * 128;
    const float* At = (FIRST ? Aext : (const float*)g_buf1) + (size_t)t * NNODE * K;
    float*       Ct = g_buf0 + (size_t)t * NNODE * GF;

    __shared__ uint32_t As32[2][128][18];
    __shared__ uint32_t Bs32[2][128][18];

    const int tid  = threadIdx.x;
    const int lane = tid & 31, wid = tid >> 5;
    const int mbase = (wid >> 1) * 32;
    const int nbase = (wid & 1) * 64;
    const int r = lane >> 2, q = lane & 3;

    float c[2][8][4];
    #pragma unroll
    for (int mt = 0; mt < 2; mt++)
        #pragma unroll
        for (int nt = 0; nt < 8; nt++)
            #pragma unroll
            for (int i = 0; i < 4; i++) c[mt][nt][i] = 0.f;

    for (int kk = 0; kk < K; kk += 32) {
        #pragma unroll
        for (int it = 0; it < 4; it++) {
            int idx = tid + it*256;
            int row = idx >> 3, c4 = idx & 7;
            float4 v = *(const float4*)(At + (size_t)(m0 + row)*K + kk + c4*4);
            float hx = __bfloat162float(__float2bfloat16(v.x));
            float hy = __bfloat162float(__float2bfloat16(v.y));
            float hz = __bfloat162float(__float2bfloat16(v.z));
            float hw = __bfloat162float(__float2bfloat16(v.w));
            As32[0][row][c4*2]   = pack_bf2(hx, hy);
            As32[0][row][c4*2+1] = pack_bf2(hz, hw);
            As32[1][row][c4*2]   = pack_bf2(v.x - hx, v.y - hy);
            As32[1][row][c4*2+1] = pack_bf2(v.z - hz, v.w - hw);
        }
        #pragma unroll
        for (int it = 0; it < 2; it++) {
            int n4 = tid & 31;
            int kp = (tid >> 5) + it*8;
            const float* bp = B + (size_t)(kk + kp*2)*GF + n4*4;
            float4 v0 = *(const float4*)(bp);
            float4 v1 = *(const float4*)(bp + GF);
            float a0[4] = {v0.x, v0.y, v0.z, v0.w};
            float a1[4] = {v1.x, v1.y, v1.z, v1.w};
            #pragma unroll
            for (int j = 0; j < 4; j++) {
                float h0 = __bfloat162float(__float2bfloat16(a0[j]));
                float h1 = __bfloat162float(__float2bfloat16(a1[j]));
                Bs32[0][n4*4 + j][kp] = pack_bf2(h0, h1);
                Bs32[1][n4*4 + j][kp] = pack_bf2(a0[j] - h0, a1[j] - h1);
            }
        }
        __syncthreads();
        #pragma unroll
        for (int s = 0; s < 2; s++) {
            uint32_t af[2][2][4];
            #pragma unroll
            for (int mt = 0; mt < 2; mt++)
                #pragma unroll
                for (int h = 0; h < 2; h++) {
                    int mrow = mbase + mt*16 + r;
                    af[mt][h][0] = As32[h][mrow    ][s*8 + q];
                    af[mt][h][1] = As32[h][mrow + 8][s*8 + q];
                    af[mt][h][2] = As32[h][mrow    ][s*8 + q + 4];
                    af[mt][h][3] = As32[h][mrow + 8][s*8 + q + 4];
                }
            #pragma unroll
            for (int nt = 0; nt < 8; nt++) {
                uint32_t bfr[2][2];
                #pragma unroll
                for (int h = 0; h < 2; h++) {
                    bfr[h][0] = Bs32[h][nbase + nt*8 + r][s*8 + q];
                    bfr[h][1] = Bs32[h][nbase + nt*8 + r][s*8 + q + 4];
                }
                #pragma unroll
                for (int mt = 0; mt < 2; mt++) {
                    mma16816(c[mt][nt], af[mt][0], bfr[0]);
                    mma16816(c[mt][nt], af[mt][0], bfr[1]);
                    mma16816(c[mt][nt], af[mt][1], bfr[0]);
                }
            }
        }
        __syncthreads();
    }
    // epilogue: scale rows by dinv, fp32 store
    #pragma unroll
    for (int mt = 0; mt < 2; mt++) {
        int row0 = m0 + mbase + mt*16 + r;
        float d0 = g_dinv[t*NNODE + row0];
        float d1 = g_dinv[t*NNODE + row0 + 8];
        #pragma unroll
        for (int nt = 0; nt < 8; nt++) {
            int col = nbase + nt*8 + 2*q;
            *(float2*)(Ct + (size_t)row0*GF + col)       = make_float2(c[mt][nt][0]*d0, c[mt][nt][1]*d0);
            *(float2*)(Ct + (size_t)(row0 + 8)*GF + col) = make_float2(c[mt][nt][2]*d1, c[mt][nt][3]*d1);
        }
    }
}

// ---------------- GCN message passing: warp-per-node, float4 rows ----------------
// Z = g_buf0 (pre-scaled by dinv). H[n] = (Z[n] + Σ_{src∈in(n)} Z[src])*dinv[n] + bias
template<bool RELU>
__global__ __launch_bounds__(256)
void k_mp(const float* __restrict__ bias) {
    int t    = blockIdx.y;
    int warp = threadIdx.x >> 5, lane = threadIdx.x & 31;
    int n    = blockIdx.x*8 + warp;
    const float4* Zt = (const float4*)(g_buf0 + (size_t)t * NNODE * GF);
    const int*    cs = g_csrc + (size_t)t*NE;

    float4 z = Zt[n*32 + lane];
    float a0 = z.x, a1 = z.y, a2 = z.z, a3 = z.w;   // self term Z[n]
    float b0 = 0.f, b1 = 0.f, b2 = 0.f, b3 = 0.f;   // second accumulator for MLP

    int e   = g_offs[t*NNODE + n];
    int end = e + g_ecnt[t*NNODE + n];
    for (; e + 1 < end; e += 2) {
        int s0 = cs[e], s1 = cs[e+1];
        float4 z0 = Zt[s0*32 + lane];
        float4 z1 = Zt[s1*32 + lane];
        a0 += z0.x; a1 += z0.y; a2 += z0.z; a3 += z0.w;
        b0 += z1.x; b1 += z1.y; b2 += z1.z; b3 += z1.w;
    }
    if (e < end) {
        int s = cs[e];
        float4 z0 = Zt[s*32 + lane];
        a0 += z0.x; a1 += z0.y; a2 += z0.z; a3 += z0.w;
    }
    float dn = g_dinv[t*NNODE + n];
    float4 bi = ((const float4*)bias)[lane];
    float4 o;
    o.x = (a0 + b0)*dn + bi.x;
    o.y = (a1 + b1)*dn + bi.y;
    o.z = (a2 + b2)*dn + bi.z;
    o.w = (a3 + b3)*dn + bi.w;
    if (RELU) {
        o.x = fmaxf(o.x, 0.f); o.y = fmaxf(o.y, 0.f);
        o.z = fmaxf(o.z, 0.f); o.w = fmaxf(o.w, 0.f);
    }
    ((float4*)(g_buf1 + (size_t)t*NNODE*GF))[n*32 + lane] = o;
}

// ---------------- FC: g_gpre[96][56] += g_buf1[96][131072] @ Wfc[131072][56] ----------------
__global__ void k_fc(const float* __restrict__ Wfc) {
    const float* Xh = g_buf1;
    __shared__ float As[96][65];
    __shared__ float Ws[64][57];
    int tid = threadIdx.x;
    int tt = tid >> 3, dd = tid & 7;
    int k0 = blockIdx.x * 512;
    float acc[3][7];
    #pragma unroll
    for (int r = 0; r < 3; r++)
        #pragma unroll
        for (int j = 0; j < 7; j++) acc[r][j] = 0.f;

    for (int sub = 0; sub < 8; sub++) {
        int kk = k0 + sub*64;
        for (int i = tid; i < 96*64; i += 256) {
            int tr = i >> 6, kl = i & 63;
            As[tr][kl] = Xh[(size_t)tr*KFC + kk + kl];
        }
        for (int i = tid; i < 64*56; i += 256) {
            int kl = i / 56, d = i - kl*56;
            Ws[kl][d] = Wfc[(size_t)(kk + kl)*56 + d];
        }
        __syncthreads();
        for (int k = 0; k < 64; k++) {
            float a0 = As[tt*3+0][k], a1 = As[tt*3+1][k], a2 = As[tt*3+2][k];
            #pragma unroll
            for (int j = 0; j < 7; j++) {
                float w = Ws[k][dd*7 + j];
                acc[0][j] += a0*w; acc[1][j] += a1*w; acc[2][j] += a2*w;
            }
        }
        __syncthreads();
    }
    #pragma unroll
    for (int r = 0; r < 3; r++)
        #pragma unroll
        for (int j = 0; j < 7; j++)
            atomicAdd(&g_gpre[(tt*3 + r)*D2W + dd*7 + j], acc[r][j]);
}

// ---------------- transpose LSTM weights ----------------
__global__ void k_trans(const float* __restrict__ Wii, const float* __restrict__ Wgi,
                        const float* __restrict__ Whi, const float* __restrict__ bi,
                        const float* __restrict__ Wif, const float* __restrict__ Wgf,
                        const float* __restrict__ Whf, const float* __restrict__ bf,
                        const float* __restrict__ Wig, const float* __restrict__ Wgg,
                        const float* __restrict__ Whg, const float* __restrict__ bg,
                        const float* __restrict__ Wio, const float* __restrict__ Wgo,
                        const float* __restrict__ Who, const float* __restrict__ bo) {
    int jp   = blockIdx.x;
    int col  = jp >> 2;
    int gate = jp & 3;
    const float* Wh = (gate == 0) ? Whi : (gate == 1) ? Whf : (gate == 2) ? Whg : Who;
    const float* Wi = (gate == 0) ? Wii : (gate == 1) ? Wif : (gate == 2) ? Wig : Wio;
    const float* Wg = (gate == 0) ? Wgi : (gate == 1) ? Wgf : (gate == 2) ? Wgg : Wgo;
    const float* bb = (gate == 0) ? bi  : (gate == 1) ? bf  : (gate == 2) ? bg  : bo;
    for (int k = threadIdx.x; k < HID; k += blockDim.x)
        g_Wht[(size_t)jp*HID + k] = Wh[(size_t)k*HID + col];
    if (threadIdx.x < INW) g_Wit[jp*INW + threadIdx.x] = Wi[threadIdx.x*HID + col];
    if (threadIdx.x < D2W) g_Wgt[jp*D2W + threadIdx.x] = Wg[threadIdx.x*HID + col];
    if (threadIdx.x == 0)  g_bpre[jp] = bb[col];
}

// ---------------- input-side gate preactivations ----------------
__global__ void k_pre(const float* __restrict__ x_in, const float* __restrict__ bfc) {
    int t  = blockIdx.y;
    int jp = blockIdx.x*blockDim.x + threadIdx.x;
    __shared__ float xg[INW];
    __shared__ float gg[D2W];
    if (threadIdx.x < INW) xg[threadIdx.x] = x_in[t*INW + threadIdx.x];
    if (threadIdx.x < D2W)
        gg[threadIdx.x] = fmaxf(g_gpre[t*D2W + threadIdx.x] + bfc[threadIdx.x], 0.f);
    __syncthreads();
    float acc = g_bpre[jp];
    const float* wi = g_Wit + jp*INW;
    #pragma unroll
    for (int k = 0; k < INW; k++) acc += xg[k]*wi[k];
    const float* wg = g_Wgt + jp*D2W;
    #pragma unroll
    for (int k = 0; k < D2W; k++) acc += gg[k]*wg[k];
    g_prega[t*4*HID + jp] = acc;
}

// ---------------- persistent LSTM ----------------
__device__ __forceinline__ float sigm(float x) { return 1.f / (1.f + expf(-x)); }

__global__ __launch_bounds__(256, 1)
void k_lstm(float* __restrict__ out, int write_hc) {
    int tid = threadIdx.x, b = blockIdx.x;
    int o_local = tid >> 3;
    int s       = tid & 7;
    int jp      = b*32 + o_local;
    float w[64];
    #pragma unroll
    for (int j = 0; j < 64; j++)
        w[j] = g_Wht[(size_t)jp*HID + j*8 + s];

    __shared__ float h_sh[HID];
    __shared__ float gates_sh[32];
    __shared__ float c_sh[8];
    if (tid < 8) c_sh[tid] = 0.f;

    for (int t = 0; t < TS; t++) {
        h_sh[tid]       = g_hbuf[(t & 1)*HID + tid];
        h_sh[tid + 256] = g_hbuf[(t & 1)*HID + tid + 256];
        __syncthreads();
        float acc = 0.f;
        #pragma unroll
        for (int j = 0; j < 64; j++) acc += w[j] * h_sh[j*8 + s];
        acc += __shfl_down_sync(0xffffffffu, acc, 4);
        acc += __shfl_down_sync(0xffffffffu, acc, 2);
        acc += __shfl_down_sync(0xffffffffu, acc, 1);
        if (s == 0) gates_sh[o_local] = acc + g_prega[t*4*HID + jp];
        __syncthreads();
        if (tid < 8) {
            float gi = gates_sh[tid*4 + 0];
            float gf = gates_sh[tid*4 + 1];
            float gc = gates_sh[tid*4 + 2];
            float go = gates_sh[tid*4 + 3];
            float i_ = sigm(gi), f_ = sigm(gf), o_ = sigm(go);
            float cc = f_*c_sh[tid] + i_*tanhf(gc);
            c_sh[tid] = cc;
            float h = o_*tanhf(cc);
            int col = b*8 + tid;
            g_hbuf[((t + 1) & 1)*HID + col] = h;
            out[t*HID + col] = h;
            if (t == TS - 1 && write_hc) {
                out[TS*HID + col]       = h;
                out[TS*HID + HID + col] = cc;
            }
            __threadfence();
        }
        __syncthreads();
        if (tid == 0) {
            __threadfence();
            atomicAdd(&g_bar, 1u);
            unsigned target = (unsigned)(t + 1) * 64u;
            while (*(volatile unsigned*)&g_bar < target) __nanosleep(64);
            __threadfence();
        }
        __syncthreads();
    }
}

// ---------------- host launch ----------------
extern "C" void kernel_launch(void* const* d_in, const int* in_sizes, int n_in,
                              void* d_out, int out_size) {
    const float* input  = (const float*)d_in[0];
    const float* xnodes = (const float*)d_in[1];
    const int*   ei     = (const int*)d_in[2];
    const float* W1  = (const float*)d_in[3];
    const float* b1  = (const float*)d_in[4];
    const float* W2  = (const float*)d_in[5];
    const float* b2  = (const float*)d_in[6];
    const float* Wfc = (const float*)d_in[7];
    const float* bfc = (const float*)d_in[8];
    const float* Wii = (const float*)d_in[9],  *Wgi = (const float*)d_in[10];
    const float* Whi = (const float*)d_in[11], *bi  = (const float*)d_in[12];
    const float* Wif = (const float*)d_in[13], *Wgf = (const float*)d_in[14];
    const float* Whf = (const float*)d_in[15], *bf  = (const float*)d_in[16];
    const float* Wig = (const float*)d_in[17], *Wgg = (const float*)d_in[18];
    const float* Whg = (const float*)d_in[19], *bg  = (const float*)d_in[20];
    const float* Wio = (const float*)d_in[21], *Wgo = (const float*)d_in[22];
    const float* Who = (const float*)d_in[23], *bo  = (const float*)d_in[24];
    float* out = (float*)d_out;

    k_init<<<(TS*NNODE + 255)/256, 256>>>();
    k_ecnt<<<(TS*NE)/256, 256>>>(ei);
    k_scan<<<TS, NNODE>>>();
    k_fill<<<(TS*NE)/256, 256>>>(ei);

    // conv1: buf0 = (x_nodes @ W1)*dinv ; buf1 = relu((Z_n + ΣZ_src)*dinv + b1)
    k_gemm_tc<true><<<dim3(8, TS), 256>>>(xnodes, W1);
    k_mp<true><<<dim3(NNODE/8, TS), 256>>>(b1);
    // conv2
    k_gemm_tc<false><<<dim3(8, TS), 256>>>(nullptr, W2);
    k_mp<false><<<dim3(NNODE/8, TS), 256>>>(b2);

    k_fc<<<256, 256>>>(Wfc);

    k_trans<<<4*HID, 128>>>(Wii, Wgi, Whi, bi, Wif, Wgf, Whf, bf,
                            Wig, Wgg, Whg, bg, Wio, Wgo, Who, bo);
    k_pre<<<dim3(8, TS), 256>>>(input, bfc);

    int whc = (out_size >= TS*HID + 2*HID) ? 1 : 0;
    k_lstm<<<64, 256>>>(out, whc);
}

// round 11
// speedup vs baseline: 1.4157x; 1.1142x over previous
#include <cuda_runtime.h>
#include <cuda_bf16.h>
#include <cstdint>

#define TS 96
#define NNODE 1024
#define GF 128
#define HID 512
#define NE 32768
#define INW 64
#define D2W 56
#define KFC (NNODE*GF)

// ---------------- static device scratch (no allocations allowed) ----------------
__device__ float g_buf0[TS*NNODE*GF];   // 50.3 MB  (GEMM outputs, pre-scaled by dinv)
__device__ float g_buf1[TS*NNODE*GF];   // 50.3 MB  (message-passing outputs)
__device__ int   g_ecnt[TS*NNODE];
__device__ int   g_offs[TS*NNODE];
__device__ float g_dinv[TS*NNODE];
__device__ int   g_csrc[TS*NE];         // 12.6 MB CSR src lists
__device__ float g_gpre[TS*D2W];
__device__ float g_prega[TS*4*HID];     // LSTM input-side gate preactivations
__device__ float g_Wht[4*HID*HID];      // transposed recurrent weights [jp][k]
__device__ float g_Wit[INW*4*HID];      // [k][jp] — coalesced for k_pre
__device__ float g_Wgt[D2W*4*HID];      // [k][jp]
__device__ float g_bpre[4*HID];
__device__ float g_hbuf[2*HID];         // h ping-pong
__device__ unsigned g_bar;

// ---------------- init: zero accumulators ----------------
__global__ void k_init() {
    int idx = blockIdx.x*blockDim.x + threadIdx.x;
    if (idx < TS*D2W) g_gpre[idx] = 0.f;
    if (idx < 2*HID)  g_hbuf[idx] = 0.f;
    if (idx == 0)     g_bar = 0u;
}

// ---------------- fused graph prep: histogram + scan + CSR fill, all in SMEM ----------------
__global__ __launch_bounds__(1024)
void k_graph(const int* __restrict__ ei) {
    int t = blockIdx.x, tid = threadIdx.x;
    __shared__ int scnt[NNODE];
    __shared__ int soff[NNODE];
    const int* srcp = ei + t*2*NE;
    const int* dstp = ei + t*2*NE + NE;

    scnt[tid] = 0;
    __syncthreads();
    #pragma unroll
    for (int i = 0; i < NE/NNODE; i++)
        atomicAdd(&scnt[dstp[i*NNODE + tid] & (NNODE-1)], 1);
    __syncthreads();

    int c = scnt[tid];
    g_ecnt[t*NNODE + tid] = c;
    g_dinv[t*NNODE + tid] = rsqrtf((float)(c + 1));   // deg incl self-loop >= 1

    soff[tid] = c;
    for (int off = 1; off < NNODE; off <<= 1) {
        __syncthreads();
        int v = (tid >= off) ? soff[tid - off] : 0;
        __syncthreads();
        soff[tid] += v;
    }
    __syncthreads();
    int excl = soff[tid] - c;
    g_offs[t*NNODE + tid] = excl;
    scnt[tid] = excl;                                  // reuse as cursor
    __syncthreads();

    #pragma unroll
    for (int i = 0; i < NE/NNODE; i++) {
        int e   = i*NNODE + tid;
        int src = srcp[e] & (NNODE-1);
        int dst = dstp[e] & (NNODE-1);
        int pos = atomicAdd(&scnt[dst], 1);
        g_csrc[(size_t)t*NE + pos] = src;
    }
}

// ---------------- bf16-split tensor-core GEMM, epilogue scales by dinv ----------------
__device__ __forceinline__ uint32_t pack_bf2(float a, float b) {
    __nv_bfloat162 h = __floats2bfloat162_rn(a, b);
    return *(uint32_t*)&h;
}
__device__ __forceinline__ void mma16816(float* c, const uint32_t* a, const uint32_t* b) {
    asm volatile(
        "mma.sync.aligned.m16n8k16.row.col.f32.bf16.bf16.f32 "
        "{%0,%1,%2,%3}, {%4,%5,%6,%7}, {%8,%9}, {%0,%1,%2,%3};\n"
        : "+f"(c[0]), "+f"(c[1]), "+f"(c[2]), "+f"(c[3])
        : "r"(a[0]), "r"(a[1]), "r"(a[2]), "r"(a[3]), "r"(b[0]), "r"(b[1]));
}

template<bool FIRST>
__global__ __launch_bounds__(256)
void k_gemm_tc(const float* __restrict__ Aext, const float* __restrict__ B) {
    constexpr int K = FIRST ? NNODE : GF;
    const int t  = blockIdx.y;
    const int m0 = blockIdx.x * 128;
    const float* At = (FIRST ? Aext : (const float*)g_buf1) + (size_t)t * NNODE * K;
    float*       Ct = g_buf0 + (size_t)t * NNODE * GF;

    __shared__ uint32_t As32[2][128][18];
    __shared__ uint32_t Bs32[2][128][18];

    const int tid  = threadIdx.x;
    const int lane = tid & 31, wid = tid >> 5;
    const int mbase = (wid >> 1) * 32;
    const int nbase = (wid & 1) * 64;
    const int r = lane >> 2, q = lane & 3;

    float c[2][8][4];
    #pragma unroll
    for (int mt = 0; mt < 2; mt++)
        #pragma unroll
        for (int nt = 0; nt < 8; nt++)
            #pragma unroll
            for (int i = 0; i < 4; i++) c[mt][nt][i] = 0.f;

    for (int kk = 0; kk < K; kk += 32) {
        #pragma unroll
        for (int it = 0; it < 4; it++) {
            int idx = tid + it*256;
            int row = idx >> 3, c4 = idx & 7;
            float4 v = *(const float4*)(At + (size_t)(m0 + row)*K + kk + c4*4);
            float hx = __bfloat162float(__float2bfloat16(v.x));
            float hy = __bfloat162float(__float2bfloat16(v.y));
            float hz = __bfloat162float(__float2bfloat16(v.z));
            float hw = __bfloat162float(__float2bfloat16(v.w));
            As32[0][row][c4*2]   = pack_bf2(hx, hy);
            As32[0][row][c4*2+1] = pack_bf2(hz, hw);
            As32[1][row][c4*2]   = pack_bf2(v.x - hx, v.y - hy);
            As32[1][row][c4*2+1] = pack_bf2(v.z - hz, v.w - hw);
        }
        #pragma unroll
        for (int it = 0; it < 2; it++) {
            int n4 = tid & 31;
            int kp = (tid >> 5) + it*8;
            const float* bp = B + (size_t)(kk + kp*2)*GF + n4*4;
            float4 v0 = *(const float4*)(bp);
            float4 v1 = *(const float4*)(bp + GF);
            float a0[4] = {v0.x, v0.y, v0.z, v0.w};
            float a1[4] = {v1.x, v1.y, v1.z, v1.w};
            #pragma unroll
            for (int j = 0; j < 4; j++) {
                float h0 = __bfloat162float(__float2bfloat16(a0[j]));
                float h1 = __bfloat162float(__float2bfloat16(a1[j]));
                Bs32[0][n4*4 + j][kp] = pack_bf2(h0, h1);
                Bs32[1][n4*4 + j][kp] = pack_bf2(a0[j] - h0, a1[j] - h1);
            }
        }
        __syncthreads();
        #pragma unroll
        for (int s = 0; s < 2; s++) {
            uint32_t af[2][2][4];
            #pragma unroll
            for (int mt = 0; mt < 2; mt++)
                #pragma unroll
                for (int h = 0; h < 2; h++) {
                    int mrow = mbase + mt*16 + r;
                    af[mt][h][0] = As32[h][mrow    ][s*8 + q];
                    af[mt][h][1] = As32[h][mrow + 8][s*8 + q];
                    af[mt][h][2] = As32[h][mrow    ][s*8 + q + 4];
                    af[mt][h][3] = As32[h][mrow + 8][s*8 + q + 4];
                }
            #pragma unroll
            for (int nt = 0; nt < 8; nt++) {
                uint32_t bfr[2][2];
                #pragma unroll
                for (int h = 0; h < 2; h++) {
                    bfr[h][0] = Bs32[h][nbase + nt*8 + r][s*8 + q];
                    bfr[h][1] = Bs32[h][nbase + nt*8 + r][s*8 + q + 4];
                }
                #pragma unroll
                for (int mt = 0; mt < 2; mt++) {
                    mma16816(c[mt][nt], af[mt][0], bfr[0]);
                    mma16816(c[mt][nt], af[mt][0], bfr[1]);
                    mma16816(c[mt][nt], af[mt][1], bfr[0]);
                }
            }
        }
        __syncthreads();
    }
    #pragma unroll
    for (int mt = 0; mt < 2; mt++) {
        int row0 = m0 + mbase + mt*16 + r;
        float d0 = g_dinv[t*NNODE + row0];
        float d1 = g_dinv[t*NNODE + row0 + 8];
        #pragma unroll
        for (int nt = 0; nt < 8; nt++) {
            int col = nbase + nt*8 + 2*q;
            *(float2*)(Ct + (size_t)row0*GF + col)       = make_float2(c[mt][nt][0]*d0, c[mt][nt][1]*d0);
            *(float2*)(Ct + (size_t)(row0 + 8)*GF + col) = make_float2(c[mt][nt][2]*d1, c[mt][nt][3]*d1);
        }
    }
}

// ---------------- GCN message passing: warp-per-node, float4 rows ----------------
template<bool RELU>
__global__ __launch_bounds__(256)
void k_mp(const float* __restrict__ bias) {
    int t    = blockIdx.y;
    int warp = threadIdx.x >> 5, lane = threadIdx.x & 31;
    int n    = blockIdx.x*8 + warp;
    const float4* Zt = (const float4*)(g_buf0 + (size_t)t * NNODE * GF);
    const int*    cs = g_csrc + (size_t)t*NE;

    float4 z = Zt[n*32 + lane];
    float a0 = z.x, a1 = z.y, a2 = z.z, a3 = z.w;
    float b0 = 0.f, b1 = 0.f, b2 = 0.f, b3 = 0.f;

    int e   = g_offs[t*NNODE + n];
    int end = e + g_ecnt[t*NNODE + n];
    for (; e + 1 < end; e += 2) {
        int s0 = cs[e], s1 = cs[e+1];
        float4 z0 = Zt[s0*32 + lane];
        float4 z1 = Zt[s1*32 + lane];
        a0 += z0.x; a1 += z0.y; a2 += z0.z; a3 += z0.w;
        b0 += z1.x; b1 += z1.y; b2 += z1.z; b3 += z1.w;
    }
    if (e < end) {
        int s = cs[e];
        float4 z0 = Zt[s*32 + lane];
        a0 += z0.x; a1 += z0.y; a2 += z0.z; a3 += z0.w;
    }
    float dn = g_dinv[t*NNODE + n];
    float4 bi = ((const float4*)bias)[lane];
    float4 o;
    o.x = (a0 + b0)*dn + bi.x;
    o.y = (a1 + b1)*dn + bi.y;
    o.z = (a2 + b2)*dn + bi.z;
    o.w = (a3 + b3)*dn + bi.w;
    if (RELU) {
        o.x = fmaxf(o.x, 0.f); o.y = fmaxf(o.y, 0.f);
        o.z = fmaxf(o.z, 0.f); o.w = fmaxf(o.w, 0.f);
    }
    ((float4*)(g_buf1 + (size_t)t*NNODE*GF))[n*32 + lane] = o;
}

// ---------------- FC: g_gpre[96][56] += g_buf1[96][131072] @ Wfc[131072][56] ----------------
__global__ void k_fc(const float* __restrict__ Wfc) {
    const float* Xh = g_buf1;
    __shared__ float As[96][65];
    __shared__ float Ws[64][57];
    int tid = threadIdx.x;
    int tt = tid >> 3, dd = tid & 7;
    int k0 = blockIdx.x * 512;
    float acc[3][7];
    #pragma unroll
    for (int r = 0; r < 3; r++)
        #pragma unroll
        for (int j = 0; j < 7; j++) acc[r][j] = 0.f;

    for (int sub = 0; sub < 8; sub++) {
        int kk = k0 + sub*64;
        for (int i = tid; i < 96*64; i += 256) {
            int tr = i >> 6, kl = i & 63;
            As[tr][kl] = Xh[(size_t)tr*KFC + kk + kl];
        }
        for (int i = tid; i < 64*56; i += 256) {
            int kl = i / 56, d = i - kl*56;
            Ws[kl][d] = Wfc[(size_t)(kk + kl)*56 + d];
        }
        __syncthreads();
        for (int k = 0; k < 64; k++) {
            float a0 = As[tt*3+0][k], a1 = As[tt*3+1][k], a2 = As[tt*3+2][k];
            #pragma unroll
            for (int j = 0; j < 7; j++) {
                float w = Ws[k][dd*7 + j];
                acc[0][j] += a0*w; acc[1][j] += a1*w; acc[2][j] += a2*w;
            }
        }
        __syncthreads();
    }
    #pragma unroll
    for (int r = 0; r < 3; r++)
        #pragma unroll
        for (int j = 0; j < 7; j++)
            atomicAdd(&g_gpre[(tt*3 + r)*D2W + dd*7 + j], acc[r][j]);
}

// ---------------- transpose LSTM weights; Wi/Wg stored [k][jp] for coalesced k_pre ----------------
__global__ void k_trans(const float* __restrict__ Wii, const float* __restrict__ Wgi,
                        const float* __restrict__ Whi, const float* __restrict__ bi,
                        const float* __restrict__ Wif, const float* __restrict__ Wgf,
                        const float* __restrict__ Whf, const float* __restrict__ bf,
                        const float* __restrict__ Wig, const float* __restrict__ Wgg,
                        const float* __restrict__ Whg, const float* __restrict__ bg,
                        const float* __restrict__ Wio, const float* __restrict__ Wgo,
                        const float* __restrict__ Who, const float* __restrict__ bo) {
    int jp   = blockIdx.x;
    int col  = jp >> 2;
    int gate = jp & 3;
    const float* Wh = (gate == 0) ? Whi : (gate == 1) ? Whf : (gate == 2) ? Whg : Who;
    const float* Wi = (gate == 0) ? Wii : (gate == 1) ? Wif : (gate == 2) ? Wig : Wio;
    const float* Wg = (gate == 0) ? Wgi : (gate == 1) ? Wgf : (gate == 2) ? Wgg : Wgo;
    const float* bb = (gate == 0) ? bi  : (gate == 1) ? bf  : (gate == 2) ? bg  : bo;
    for (int k = threadIdx.x; k < HID; k += blockDim.x)
        g_Wht[(size_t)jp*HID + k] = Wh[(size_t)k*HID + col];
    if (threadIdx.x < INW) g_Wit[threadIdx.x*4*HID + jp] = Wi[threadIdx.x*HID + col];
    if (threadIdx.x < D2W) g_Wgt[threadIdx.x*4*HID + jp] = Wg[threadIdx.x*HID + col];
    if (threadIdx.x == 0)  g_bpre[jp] = bb[col];
}

// ---------------- input-side gate preactivations (coalesced weight reads) ----------------
__global__ void k_pre(const float* __restrict__ x_in, const float* __restrict__ bfc) {
    int t  = blockIdx.y;
    int jp = blockIdx.x*blockDim.x + threadIdx.x;
    __shared__ float xg[INW];
    __shared__ float gg[D2W];
    if (threadIdx.x < INW) xg[threadIdx.x] = x_in[t*INW + threadIdx.x];
    if (threadIdx.x < D2W)
        gg[threadIdx.x] = fmaxf(g_gpre[t*D2W + threadIdx.x] + bfc[threadIdx.x], 0.f);
    __syncthreads();
    float acc = g_bpre[jp];
    #pragma unroll
    for (int k = 0; k < INW; k++) acc += xg[k] * g_Wit[k*4*HID + jp];
    #pragma unroll
    for (int k = 0; k < D2W; k++) acc += gg[k] * g_Wgt[k*4*HID + jp];
    g_prega[t*4*HID + jp] = acc;
}

// ---------------- persistent LSTM: 64 blocks, grid barrier per step ----------------
__device__ __forceinline__ float sigm(float x) { return 1.f / (1.f + expf(-x)); }

__global__ __launch_bounds__(256, 1)
void k_lstm(float* __restrict__ out, int write_hc) {
    int tid = threadIdx.x, b = blockIdx.x;
    int o_local = tid >> 3;
    int s       = tid & 7;
    int jp      = b*32 + o_local;
    float w[64];
    #pragma unroll
    for (int j = 0; j < 64; j++)
        w[j] = g_Wht[(size_t)jp*HID + j*8 + s];

    __shared__ float h_sh[HID];
    __shared__ float gates_sh[32];
    __shared__ float c_sh[8];
    if (tid < 8) c_sh[tid] = 0.f;

    for (int t = 0; t < TS; t++) {
        h_sh[tid]       = g_hbuf[(t & 1)*HID + tid];
        h_sh[tid + 256] = g_hbuf[(t & 1)*HID + tid + 256];
        __syncthreads();
        float acc = 0.f;
        #pragma unroll
        for (int j = 0; j < 64; j++) acc += w[j] * h_sh[j*8 + s];
        acc += __shfl_down_sync(0xffffffffu, acc, 4);
        acc += __shfl_down_sync(0xffffffffu, acc, 2);
        acc += __shfl_down_sync(0xffffffffu, acc, 1);
        if (s == 0) gates_sh[o_local] = acc + g_prega[t*4*HID + jp];
        __syncthreads();
        if (tid < 8) {
            float gi = gates_sh[tid*4 + 0];
            float gf = gates_sh[tid*4 + 1];
            float gc = gates_sh[tid*4 + 2];
            float go = gates_sh[tid*4 + 3];
            float i_ = sigm(gi), f_ = sigm(gf), o_ = sigm(go);
            float cc = f_*c_sh[tid] + i_*tanhf(gc);
            c_sh[tid] = cc;
            float h = o_*tanhf(cc);
            int col = b*8 + tid;
            g_hbuf[((t + 1) & 1)*HID + col] = h;
            out[t*HID + col] = h;
            if (t == TS - 1 && write_hc) {
                out[TS*HID + col]       = h;
                out[TS*HID + HID + col] = cc;
            }
        }
        __syncthreads();
        if (tid == 0) {
            __threadfence();
            atomicAdd(&g_bar, 1u);
            unsigned target = (unsigned)(t + 1) * 64u;
            while (*(volatile unsigned*)&g_bar < target) __nanosleep(32);
            __threadfence();
        }
        __syncthreads();
    }
}

// ---------------- host launch: ordered so ncu slot #4 = k_gemm_tc<true> ----------------
extern "C" void kernel_launch(void* const* d_in, const int* in_sizes, int n_in,
                              void* d_out, int out_size) {
    const float* input  = (const float*)d_in[0];
    const float* xnodes = (const float*)d_in[1];
    const int*   ei     = (const int*)d_in[2];
    const float* W1  = (const float*)d_in[3];
    const float* b1  = (const float*)d_in[4];
    const float* W2  = (const float*)d_in[5];
    const float* b2  = (const float*)d_in[6];
    const float* Wfc = (const float*)d_in[7];
    const float* bfc = (const float*)d_in[8];
    const float* Wii = (const float*)d_in[9],  *Wgi = (const float*)d_in[10];
    const float* Whi = (const float*)d_in[11], *bi  = (const float*)d_in[12];
    const float* Wif = (const float*)d_in[13], *Wgf = (const float*)d_in[14];
    const float* Whf = (const float*)d_in[15], *bf  = (const float*)d_in[16];
    const float* Wig = (const float*)d_in[17], *Wgg = (const float*)d_in[18];
    const float* Whg = (const float*)d_in[19], *bg  = (const float*)d_in[20];
    const float* Wio = (const float*)d_in[21], *Wgo = (const float*)d_in[22];
    const float* Who = (const float*)d_in[23], *bo  = (const float*)d_in[24];
    float* out = (float*)d_out;

    k_init<<<24, 256>>>();                               // 1
    k_trans<<<4*HID, 128>>>(Wii, Wgi, Whi, bi,           // 2
                            Wif, Wgf, Whf, bf,
                            Wig, Wgg, Whg, bg,
                            Wio, Wgo, Who, bo);
    k_graph<<<TS, NNODE>>>(ei);                          // 3  (hist+scan+fill in smem)
    k_gemm_tc<true><<<dim3(8, TS), 256>>>(xnodes, W1);   // 4  <- ncu capture slot
    k_mp<true><<<dim3(NNODE/8, TS), 256>>>(b1);          // 5
    k_gemm_tc<false><<<dim3(8, TS), 256>>>(nullptr, W2); // 6
    k_mp<false><<<dim3(NNODE/8, TS), 256>>>(b2);         // 7
    k_fc<<<256, 256>>>(Wfc);                             // 8
    k_pre<<<dim3(8, TS), 256>>>(input, bfc);             // 9
    int whc = (out_size >= TS*HID + 2*HID) ? 1 : 0;
    k_lstm<<<64, 256>>>(out, whc);                       // 10
}